// round 15
// baseline (speedup 1.0000x reference)
#include <cuda_runtime.h>
#include <cuda_fp16.h>
#include <cstdint>

// ============================================================
// Problem constants
// ============================================================
#define M_TOTAL   65536          // B*NP = 16*4096
#define K_DIM     768
#define N_DIM     1152
#define POS_SIZE  64

// Tiling: CTA 256x128, 8 warps (4m x 2n), warp tile 64x64 (acc = 128 regs)
#define M_TILE    256
#define N_TILE    128
#define K_CHUNK   64                       // fp16 elems per pipeline chunk
#define NUM_CHUNKS (K_DIM / K_CHUNK)       // 12
#define STAGES    3

// SMEM rows: 128B data + 16B pad = 144B (R10-proven conflict-free:
// 16r mod 128 distinct for r=0..7).
#define ROW_BYTES   144
#define A_TILE_B    (256 * ROW_BYTES)          // 36864
#define B_TILE_B    (128 * ROW_BYTES)          // 18432
#define STAGE_BYTES (A_TILE_B + B_TILE_B)      // 55296
#define SMEM_TOTAL  (STAGES * STAGE_BYTES)     // 165888 (1 CTA/SM, <= 227KB)

// ============================================================
// Scratch (device globals -- no allocation)
// ============================================================
__device__ __align__(256) __half g_A[(size_t)M_TOTAL * K_DIM];   // 96 MB
__device__ __align__(256) __half g_B[(size_t)N_DIM * K_DIM];     // 1.7 MB
__device__ int g_pos_is_i32;    // 1 if position ids are int32, 0 if int64
__device__ int g_pad_is_i32;    // 1 if padding mask is int32, 0 if 1-byte bool

// ============================================================
// Dtype detectors (verified R6-R13).
// ============================================================
__global__ void detect_kernel(const int* __restrict__ pos,
                              const int* __restrict__ padw) {
    __shared__ int sh[256];
    int acc = 0;
    if (blockIdx.x == 0) {
        for (int t = threadIdx.x; t < 2048; t += 256)
            acc |= pos[2 * t + 1];
    } else {
        for (int t = threadIdx.x; t < 16384; t += 256)
            acc |= (padw[t] & ~1);     // any bit beyond bit0 -> byte layout
    }
    sh[threadIdx.x] = acc;
    __syncthreads();
    for (int s = 128; s > 0; s >>= 1) {
        if (threadIdx.x < s) sh[threadIdx.x] |= sh[threadIdx.x + s];
        __syncthreads();
    }
    if (threadIdx.x == 0) {
        if (blockIdx.x == 0) g_pos_is_i32 = (sh[0] != 0) ? 1 : 0;
        else                 g_pad_is_i32 = (sh[0] != 0) ? 0 : 1;
    }
}

// ============================================================
// Helpers
// ============================================================
__device__ __forceinline__ uint32_t smem_u32(const void* p) {
    uint32_t a;
    asm("{ .reg .u64 t; cvta.to.shared.u64 t, %1; cvt.u32.u64 %0, t; }"
        : "=r"(a) : "l"(p));
    return a;
}

#define CP_ASYNC16(saddr, gptr) \
    asm volatile("cp.async.cg.shared.global [%0], [%1], 16;" \
                 :: "r"(saddr), "l"(gptr) : "memory")
#define CP_COMMIT() asm volatile("cp.async.commit_group;" ::: "memory")
#define CP_WAIT1()  asm volatile("cp.async.wait_group 1;" ::: "memory")

#define LDMX4(R, addr) \
    asm volatile("ldmatrix.sync.aligned.m8n8.x4.shared.b16 {%0,%1,%2,%3}, [%4];" \
        : "=r"((R)[0]), "=r"((R)[1]), "=r"((R)[2]), "=r"((R)[3]) : "r"(addr))

// mma.sync m16n8k16 row.col f32.f16.f16.f32 (verified fragment layouts)
#define MMA16816(C, A, B) \
    asm volatile("mma.sync.aligned.m16n8k16.row.col.f32.f16.f16.f32 " \
        "{%0,%1,%2,%3}, {%4,%5,%6,%7}, {%8,%9}, {%0,%1,%2,%3};" \
        : "+f"((C)[0]), "+f"((C)[1]), "+f"((C)[2]), "+f"((C)[3]) \
        : "r"((A)[0]), "r"((A)[1]), "r"((A)[2]), "r"((A)[3]), \
          "r"((B)[0]), "r"((B)[1]))

// ============================================================
// Prep kernels: fp32 -> fp16
// ============================================================
__device__ __forceinline__ uint2 cvt4(float4 v) {
    __half2 h0 = __floats2half2_rn(v.x, v.y);
    __half2 h1 = __floats2half2_rn(v.z, v.w);
    uint2 o;
    o.x = *reinterpret_cast<uint32_t*>(&h0);
    o.y = *reinterpret_cast<uint32_t*>(&h1);
    return o;
}

__global__ void prep_a_kernel(const float4* __restrict__ src, int n4) {
    int i = blockIdx.x * blockDim.x + threadIdx.x;
    if (i < n4) reinterpret_cast<uint2*>(g_A)[i] = cvt4(src[i]);
}

__global__ void prep_b_kernel(const float4* __restrict__ src, int n4) {
    int i = blockIdx.x * blockDim.x + threadIdx.x;
    if (i < n4) reinterpret_cast<uint2*>(g_B)[i] = cvt4(src[i]);
}

// ============================================================
// GEMM + positional-embedding epilogue
//   grid = (N_DIM/128, M_TOTAL/256), block = 256 (8 warps)
//   warp grid 4(m) x 2(n): warp tile 64 x 64
// ============================================================
__global__ void __launch_bounds__(256, 1) gemm_kernel(
    const void* __restrict__ pos_raw,           // [M_TOTAL, 2] i32 or i64
    const void* __restrict__ pad_raw,           // [M_TOTAL] i32 or u8
    const float* __restrict__ table,            // [2, 64, 1152] f32
    float* __restrict__ out)                    // [M_TOTAL, 1152] f32
{
    extern __shared__ char smem[];
    const uint32_t sbase = smem_u32(smem);
    const int tid  = threadIdx.x;
    const int lane = tid & 31;
    const int wid  = tid >> 5;
    const int wm   = wid & 3;          // 0..3  -> rows 64*wm
    const int wn   = wid >> 2;         // 0..1  -> cols 64*wn
    const int m_base = blockIdx.y * M_TILE;
    const int n_base = blockIdx.x * N_TILE;

    const __half* gA = g_A + (size_t)m_base * K_DIM;
    const __half* gB = g_B + (size_t)n_base * K_DIM;

    // cp.async decomposition: per chunk A = 256 rows x 8 segs = 2048 units,
    // B = 128 rows x 8 segs = 1024 units; total 3072 = 256 threads x 12.
    auto load_chunk = [&](int c, int stage) {
        const uint32_t s = sbase + (uint32_t)stage * STAGE_BYTES;
        const int kb = c * K_CHUNK;
#pragma unroll
        for (int t = 0; t < 12; t++) {
            const int u = tid + 256 * t;
            if (u < 2048) {
                const int row = u >> 3, sg = u & 7;
                uint32_t sa = s + (uint32_t)(row * ROW_BYTES + sg * 16);
                CP_ASYNC16(sa, gA + (size_t)row * K_DIM + kb + sg * 8);
            } else {
                const int v = u - 2048;
                const int row = v >> 3, sg = v & 7;
                uint32_t sb = s + A_TILE_B + (uint32_t)(row * ROW_BYTES + sg * 16);
                CP_ASYNC16(sb, gB + (size_t)row * K_DIM + kb + sg * 8);
            }
        }
        CP_COMMIT();
    };

    float acc[4][8][4];
#pragma unroll
    for (int i = 0; i < 4; i++)
#pragma unroll
        for (int j = 0; j < 8; j++)
#pragma unroll
            for (int e = 0; e < 4; e++) acc[i][j][e] = 0.0f;

    load_chunk(0, 0);
    load_chunk(1, 1);

    // ldmatrix lane addresses (verified R7-R13), ROW_BYTES=144.
    const uint32_t a_lane = (uint32_t)((lane & 15) * ROW_BYTES + (lane >> 4) * 16);
    const uint32_t b_lane = (uint32_t)(((lane & 7) + ((lane >> 4) << 3)) * ROW_BYTES
                                       + (((lane >> 3) & 1) << 4));

#pragma unroll 1
    for (int c = 0; c < NUM_CHUNKS; c++) {
        CP_WAIT1();          // <=1 group pending => group c complete
        __syncthreads();

        const uint32_t stg = sbase + (uint32_t)(c % 3) * STAGE_BYTES;
        const uint32_t As = stg + (uint32_t)(wm * 64 * ROW_BYTES) + a_lane;
        const uint32_t Bs = stg + A_TILE_B + (uint32_t)(wn * 64 * ROW_BYTES) + b_lane;

#pragma unroll
        for (int ks = 0; ks < 4; ks++) {
            uint32_t bf[8][2];
#pragma unroll
            for (int jj = 0; jj < 4; jj++) {
                uint32_t t4[4];
                LDMX4(t4, Bs + jj * 16 * ROW_BYTES + ks * 32);
                bf[2 * jj][0]     = t4[0];
                bf[2 * jj][1]     = t4[1];
                bf[2 * jj + 1][0] = t4[2];
                bf[2 * jj + 1][1] = t4[3];
            }
#pragma unroll
            for (int i = 0; i < 4; i++) {
                uint32_t af[4];
                LDMX4(af, As + i * 16 * ROW_BYTES + ks * 32);
#pragma unroll
                for (int j = 0; j < 8; j++)
                    MMA16816(acc[i][j], af, bf[j]);
            }
        }

        // Stage (c+2)%3's previous tenant (chunk c-1) was fully read in iter
        // c-1, before this iteration's __syncthreads: safe to overwrite.
        if (c + 2 < NUM_CHUNKS) {
            load_chunk(c + 2, (c + 2) % 3);
        } else {
            CP_COMMIT();   // empty group keeps wait_group accounting correct
        }
    }

    // ---------------- Epilogue (verified R6-R13): + pos embedding, store ----
    const int r4 = lane >> 2;
    const int qc = (lane & 3) * 2;
    const int pos_i32 = g_pos_is_i32;
    const int pad_i32 = g_pad_is_i32;
    const int* p32 = (const int*)pos_raw;
    const long long* p64 = (const long long*)pos_raw;
    const int* pd32 = (const int*)pad_raw;
    const unsigned char* pd8 = (const unsigned char*)pad_raw;

#pragma unroll
    for (int i = 0; i < 4; i++) {
#pragma unroll
        for (int rh = 0; rh < 2; rh++) {
            const int m = m_base + wm * 64 + i * 16 + rh * 8 + r4;
            int xr, yr;
            if (pos_i32) {
                xr = p32[(size_t)m * 2 + 0];
                yr = p32[(size_t)m * 2 + 1];
            } else {
                long long pxv = p64[(size_t)m * 2 + 0];
                long long pyv = p64[(size_t)m * 2 + 1];
                xr = (pxv < 0) ? 0 : (pxv > 63 ? 63 : (int)pxv);
                yr = (pyv < 0) ? 0 : (pyv > 63 ? 63 : (int)pyv);
            }
            const int xi = (xr < 0) ? 0 : (xr > 63 ? 63 : xr);
            const int yi = (yr < 0) ? 0 : (yr > 63 ? 63 : yr);
            const bool pd = pad_i32 ? (pd32[m] != 0) : (pd8[m] != 0);
            const float* t0 = table + (size_t)xi * N_DIM;
            const float* t1 = table + (size_t)(POS_SIZE + yi) * N_DIM;
            float* orow = out + (size_t)m * N_DIM;
#pragma unroll
            for (int j = 0; j < 8; j++) {
                const int n = n_base + wn * 64 + j * 8 + qc;
                float v0 = acc[i][j][rh * 2 + 0];
                float v1 = acc[i][j][rh * 2 + 1];
                if (!pd) {
                    const float2 a = *reinterpret_cast<const float2*>(t0 + n);
                    const float2 b = *reinterpret_cast<const float2*>(t1 + n);
                    v0 += a.x + b.x;
                    v1 += a.y + b.y;
                }
                float2 o; o.x = v0; o.y = v1;
                *reinterpret_cast<float2*>(orow + n) = o;
            }
        }
    }
}

// ============================================================
// Launch — inputs identified by element count (all distinct):
//   pixel_values 50331648, pos 131072, pad 65536, W 884736, table 147456
// ============================================================
extern "C" void kernel_launch(void* const* d_in, const int* in_sizes, int n_in,
                              void* d_out, int out_size) {
    const float* px = nullptr;
    const void*  pos = nullptr;
    const void*  pad = nullptr;
    const float* W = nullptr;
    const float* table = nullptr;

    for (int i = 0; i < n_in; i++) {
        switch (in_sizes[i]) {
            case 50331648: px    = (const float*)d_in[i]; break;
            case 131072:   pos   = d_in[i];               break;
            case 65536:    pad   = d_in[i];               break;
            case 884736:   W     = (const float*)d_in[i]; break;
            case 147456:   table = (const float*)d_in[i]; break;
            default: break;
        }
    }
    if (!px)    px    = (const float*)d_in[0];
    if (!pos)   pos   = d_in[1];
    if (!pad)   pad   = d_in[2];
    if (!W)     W     = (const float*)d_in[3];
    if (!table) table = (const float*)d_in[4];

    float* out = (float*)d_out;

    detect_kernel<<<2, 256>>>((const int*)pos, (const int*)pad);

    const int n4a = (M_TOTAL * K_DIM) / 4;   // 12,582,912
    const int n4b = (N_DIM * K_DIM) / 4;     // 221,184
    prep_a_kernel<<<(n4a + 255) / 256, 256>>>((const float4*)px, n4a);
    prep_b_kernel<<<(n4b + 255) / 256, 256>>>((const float4*)W, n4b);

    cudaFuncSetAttribute(gemm_kernel, cudaFuncAttributeMaxDynamicSharedMemorySize,
                         SMEM_TOTAL);
    dim3 grid(N_DIM / N_TILE, M_TOTAL / M_TILE);   // (9, 256) — N fastest: A reuse
    gemm_kernel<<<grid, 256, SMEM_TOTAL>>>(pos, pad, table, out);
}

// round 16
// speedup vs baseline: 1.1426x; 1.1426x over previous
#include <cuda_runtime.h>
#include <cuda_fp16.h>
#include <cstdint>

// ============================================================
// Problem constants
// ============================================================
#define M_TOTAL   65536          // B*NP = 16*4096
#define K_DIM     768
#define N_DIM     1152
#define POS_SIZE  64

// Tiling (R10-proven): CTA 128x128, 4 warps (2m x 2n), warp tile 64x64
#define M_TILE    128
#define N_TILE    128
#define K_CHUNK   64                       // fp16 elems per pipeline chunk
#define NUM_CHUNKS (K_DIM / K_CHUNK)       // 12
#define STAGES    2

// SMEM rows: 128B data + 16B pad = 144B (R10-proven conflict-free:
// 16r mod 128 distinct for r=0..7).
#define ROW_BYTES   144
#define TILE_BYTES  (128 * ROW_BYTES)      // 18432
#define STAGE_BYTES (2 * TILE_BYTES)       // 36864 (A then B)
#define SMEM_TOTAL  (STAGES * STAGE_BYTES) // 73728 (3 CTAs = 221184B <= 228KB)

// ============================================================
// Scratch (device globals -- no allocation)
// ============================================================
__device__ __align__(256) __half g_A[(size_t)M_TOTAL * K_DIM];   // 96 MB
__device__ __align__(256) __half g_B[(size_t)N_DIM * K_DIM];     // 1.7 MB
__device__ int g_pos_is_i32;    // 1 if position ids are int32, 0 if int64
__device__ int g_pad_is_i32;    // 1 if padding mask is int32, 0 if 1-byte bool

// ============================================================
// Helpers
// ============================================================
__device__ __forceinline__ uint32_t smem_u32(const void* p) {
    uint32_t a;
    asm("{ .reg .u64 t; cvta.to.shared.u64 t, %1; cvt.u32.u64 %0, t; }"
        : "=r"(a) : "l"(p));
    return a;
}

#define CP_ASYNC16(saddr, gptr) \
    asm volatile("cp.async.cg.shared.global [%0], [%1], 16;" \
                 :: "r"(saddr), "l"(gptr) : "memory")
#define CP_COMMIT() asm volatile("cp.async.commit_group;" ::: "memory")
#define CP_WAIT0()  asm volatile("cp.async.wait_group 0;" ::: "memory")

#define LDMX4(R, addr) \
    asm volatile("ldmatrix.sync.aligned.m8n8.x4.shared.b16 {%0,%1,%2,%3}, [%4];" \
        : "=r"((R)[0]), "=r"((R)[1]), "=r"((R)[2]), "=r"((R)[3]) : "r"(addr))

// mma.sync m16n8k16 row.col f32.f16.f16.f32 (verified fragment layouts)
#define MMA16816(C, A, B) \
    asm volatile("mma.sync.aligned.m16n8k16.row.col.f32.f16.f16.f32 " \
        "{%0,%1,%2,%3}, {%4,%5,%6,%7}, {%8,%9}, {%0,%1,%2,%3};" \
        : "+f"((C)[0]), "+f"((C)[1]), "+f"((C)[2]), "+f"((C)[3]) \
        : "r"((A)[0]), "r"((A)[1]), "r"((A)[2]), "r"((A)[3]), \
          "r"((B)[0]), "r"((B)[1]))

// ============================================================
// Fused prep: fp32->fp16 for A and B, plus dtype detectors, one launch.
//   blocks [0, NBLK_A)            : convert A (px -> g_A)
//   blocks [NBLK_A, NBLK_A+NBLK_B): convert B (W -> g_B)
//   block  NBLK_A+NBLK_B          : pos dtype detect
//   block  NBLK_A+NBLK_B+1        : pad dtype detect
// ============================================================
#define N4A (M_TOTAL * K_DIM / 4)          // 12,582,912
#define N4B (N_DIM * K_DIM / 4)            // 221,184
#define NBLK_A (N4A / 256)                 // 49152
#define NBLK_B (N4B / 256)                 // 864

__device__ __forceinline__ uint2 cvt4(float4 v) {
    __half2 h0 = __floats2half2_rn(v.x, v.y);
    __half2 h1 = __floats2half2_rn(v.z, v.w);
    uint2 o;
    o.x = *reinterpret_cast<uint32_t*>(&h0);
    o.y = *reinterpret_cast<uint32_t*>(&h1);
    return o;
}

__global__ void prep_kernel(const float4* __restrict__ px,
                            const float4* __restrict__ W,
                            const int* __restrict__ pos,
                            const int* __restrict__ padw) {
    const int bid = blockIdx.x;
    if (bid < NBLK_A) {
        const int i = bid * 256 + threadIdx.x;
        reinterpret_cast<uint2*>(g_A)[i] = cvt4(px[i]);
        return;
    }
    if (bid < NBLK_A + NBLK_B) {
        const int i = (bid - NBLK_A) * 256 + threadIdx.x;
        reinterpret_cast<uint2*>(g_B)[i] = cvt4(W[i]);
        return;
    }
    // Detectors (verified R6-R14).
    __shared__ int sh[256];
    int acc = 0;
    const int which = bid - (NBLK_A + NBLK_B);
    if (which == 0) {
        for (int t = threadIdx.x; t < 2048; t += 256)
            acc |= pos[2 * t + 1];
    } else {
        for (int t = threadIdx.x; t < 16384; t += 256)
            acc |= (padw[t] & ~1);     // any bit beyond bit0 -> byte layout
    }
    sh[threadIdx.x] = acc;
    __syncthreads();
    for (int s = 128; s > 0; s >>= 1) {
        if (threadIdx.x < s) sh[threadIdx.x] |= sh[threadIdx.x + s];
        __syncthreads();
    }
    if (threadIdx.x == 0) {
        if (which == 0) g_pos_is_i32 = (sh[0] != 0) ? 1 : 0;
        else            g_pad_is_i32 = (sh[0] != 0) ? 0 : 1;
    }
}

// ============================================================
// GEMM + positional-embedding epilogue
//   grid = (N_DIM/128, M_TOTAL/128), block = 128 (4 warps)
//   warp grid 2(m) x 2(n): warp tile 64 x 64.  3 CTAs/SM.
// ============================================================
__global__ void __launch_bounds__(128, 3) gemm_kernel(
    const void* __restrict__ pos_raw,           // [M_TOTAL, 2] i32 or i64
    const void* __restrict__ pad_raw,           // [M_TOTAL] i32 or u8
    const float* __restrict__ table,            // [2, 64, 1152] f32
    float* __restrict__ out)                    // [M_TOTAL, 1152] f32
{
    extern __shared__ char smem[];
    const uint32_t sbase = smem_u32(smem);
    const int tid  = threadIdx.x;
    const int lane = tid & 31;
    const int wid  = tid >> 5;
    const int wm   = wid & 1;          // 0..1  -> rows 64*wm
    const int wn   = wid >> 1;         // 0..1  -> cols 64*wn
    const int m_base = blockIdx.y * M_TILE;
    const int n_base = blockIdx.x * N_TILE;

    const __half* gA = g_A + (size_t)m_base * K_DIM;
    const __half* gB = g_B + (size_t)n_base * K_DIM;

    // cp.async decomposition: per tile 128 rows x 128B = 1024 x 16B units;
    // 128 threads x 8 units (unit u = tid + 128*t: row = u>>3, seg = u&7).
    auto load_chunk = [&](int c, int stage) {
        const uint32_t s = sbase + (uint32_t)stage * STAGE_BYTES;
        const int kb = c * K_CHUNK;
#pragma unroll
        for (int t = 0; t < 8; t++) {
            const int u = tid + 128 * t;
            const int row = u >> 3, sg = u & 7;
            uint32_t sa = s + (uint32_t)(row * ROW_BYTES + sg * 16);
            CP_ASYNC16(sa, gA + (size_t)row * K_DIM + kb + sg * 8);
            CP_ASYNC16(sa + TILE_BYTES, gB + (size_t)row * K_DIM + kb + sg * 8);
        }
        CP_COMMIT();
    };

    float acc[4][8][4];
#pragma unroll
    for (int i = 0; i < 4; i++)
#pragma unroll
        for (int j = 0; j < 8; j++)
#pragma unroll
            for (int e = 0; e < 4; e++) acc[i][j][e] = 0.0f;

    load_chunk(0, 0);

    // ldmatrix lane addresses (verified R7-R14), ROW_BYTES=144.
    const uint32_t a_lane = (uint32_t)((lane & 15) * ROW_BYTES + (lane >> 4) * 16);
    const uint32_t b_lane = (uint32_t)(((lane & 7) + ((lane >> 4) << 3)) * ROW_BYTES
                                       + (((lane >> 3) & 1) << 4));

#pragma unroll 1
    for (int c = 0; c < NUM_CHUNKS; c++) {
        CP_WAIT0();          // chunk c resident
        __syncthreads();     // visibility + all warps done with chunk c-1

        // Refill the buffer freed by chunk c-1 (computed before the sync).
        if (c + 1 < NUM_CHUNKS) load_chunk(c + 1, (c + 1) & 1);

        const uint32_t stg = sbase + (uint32_t)(c & 1) * STAGE_BYTES;
        const uint32_t As = stg + (uint32_t)(wm * 64 * ROW_BYTES) + a_lane;
        const uint32_t Bs = stg + TILE_BYTES + (uint32_t)(wn * 64 * ROW_BYTES) + b_lane;

#pragma unroll
        for (int ks = 0; ks < 4; ks++) {
            uint32_t bf[8][2];
#pragma unroll
            for (int jj = 0; jj < 4; jj++) {
                uint32_t t4[4];
                LDMX4(t4, Bs + jj * 16 * ROW_BYTES + ks * 32);
                bf[2 * jj][0]     = t4[0];
                bf[2 * jj][1]     = t4[1];
                bf[2 * jj + 1][0] = t4[2];
                bf[2 * jj + 1][1] = t4[3];
            }
#pragma unroll
            for (int i = 0; i < 4; i++) {
                uint32_t af[4];
                LDMX4(af, As + i * 16 * ROW_BYTES + ks * 32);
#pragma unroll
                for (int j = 0; j < 8; j++)
                    MMA16816(acc[i][j], af, bf[j]);
            }
        }
    }

    // ---------------- Epilogue (verified R6-R14): + pos embedding, store ----
    const int r4 = lane >> 2;
    const int qc = (lane & 3) * 2;
    const int pos_i32 = g_pos_is_i32;
    const int pad_i32 = g_pad_is_i32;
    const int* p32 = (const int*)pos_raw;
    const long long* p64 = (const long long*)pos_raw;
    const int* pd32 = (const int*)pad_raw;
    const unsigned char* pd8 = (const unsigned char*)pad_raw;

#pragma unroll
    for (int i = 0; i < 4; i++) {
#pragma unroll
        for (int rh = 0; rh < 2; rh++) {
            const int m = m_base + wm * 64 + i * 16 + rh * 8 + r4;
            int xr, yr;
            if (pos_i32) {
                xr = p32[(size_t)m * 2 + 0];
                yr = p32[(size_t)m * 2 + 1];
            } else {
                long long pxv = p64[(size_t)m * 2 + 0];
                long long pyv = p64[(size_t)m * 2 + 1];
                xr = (pxv < 0) ? 0 : (pxv > 63 ? 63 : (int)pxv);
                yr = (pyv < 0) ? 0 : (pyv > 63 ? 63 : (int)pyv);
            }
            const int xi = (xr < 0) ? 0 : (xr > 63 ? 63 : xr);
            const int yi = (yr < 0) ? 0 : (yr > 63 ? 63 : yr);
            const bool pd = pad_i32 ? (pd32[m] != 0) : (pd8[m] != 0);
            const float* t0 = table + (size_t)xi * N_DIM;
            const float* t1 = table + (size_t)(POS_SIZE + yi) * N_DIM;
            float* orow = out + (size_t)m * N_DIM;
#pragma unroll
            for (int j = 0; j < 8; j++) {
                const int n = n_base + wn * 64 + j * 8 + qc;
                float v0 = acc[i][j][rh * 2 + 0];
                float v1 = acc[i][j][rh * 2 + 1];
                if (!pd) {
                    const float2 a = *reinterpret_cast<const float2*>(t0 + n);
                    const float2 b = *reinterpret_cast<const float2*>(t1 + n);
                    v0 += a.x + b.x;
                    v1 += a.y + b.y;
                }
                float2 o; o.x = v0; o.y = v1;
                *reinterpret_cast<float2*>(orow + n) = o;
            }
        }
    }
}

// ============================================================
// Launch — inputs identified by element count (all distinct):
//   pixel_values 50331648, pos 131072, pad 65536, W 884736, table 147456
// ============================================================
extern "C" void kernel_launch(void* const* d_in, const int* in_sizes, int n_in,
                              void* d_out, int out_size) {
    const float* px = nullptr;
    const void*  pos = nullptr;
    const void*  pad = nullptr;
    const float* W = nullptr;
    const float* table = nullptr;

    for (int i = 0; i < n_in; i++) {
        switch (in_sizes[i]) {
            case 50331648: px    = (const float*)d_in[i]; break;
            case 131072:   pos   = d_in[i];               break;
            case 65536:    pad   = d_in[i];               break;
            case 884736:   W     = (const float*)d_in[i]; break;
            case 147456:   table = (const float*)d_in[i]; break;
            default: break;
        }
    }
    if (!px)    px    = (const float*)d_in[0];
    if (!pos)   pos   = d_in[1];
    if (!pad)   pad   = d_in[2];
    if (!W)     W     = (const float*)d_in[3];
    if (!table) table = (const float*)d_in[4];

    float* out = (float*)d_out;

    prep_kernel<<<NBLK_A + NBLK_B + 2, 256>>>(
        (const float4*)px, (const float4*)W, (const int*)pos, (const int*)pad);

    cudaFuncSetAttribute(gemm_kernel, cudaFuncAttributeMaxDynamicSharedMemorySize,
                         SMEM_TOTAL);
    dim3 grid(N_DIM / N_TILE, M_TOTAL / M_TILE);   // (9, 512) — N fastest: A reuse
    gemm_kernel<<<grid, 128, SMEM_TOTAL>>>(pos, pad, table, out);
}